// round 1
// baseline (speedup 1.0000x reference)
#include <cuda_runtime.h>
#include <math.h>

// Problem constants (fixed by the reference)
#define BB 4
#define SS 4096
#define DF 1024
#define HH 16
#define HD 64
#define SK 1024          // SS / STRIDE
#define STRIDE 4
#define BQ 16            // q rows per CTA
#define CK 128           // k/v rows per smem chunk
#define KST 68           // padded floats per smem row (conflict-free LDS.128)
#define NCHUNK (SK / CK) // 8
#define NTHREADS 256

// smem layout (floats):
//   q_tile  [BQ][HD]        = 1024
//   kv_tile [CK][KST]       = 8704
//   scores  [BQ][SK]        = 16384
#define SM_Q   0
#define SM_KV  (SM_Q + BQ * HD)
#define SM_SC  (SM_KV + CK * KST)
#define SM_FLOATS (SM_SC + BQ * SK)
#define SM_BYTES (SM_FLOATS * 4)

__global__ __launch_bounds__(NTHREADS, 2)
void sparse_attn_kernel(const float* __restrict__ q,
                        const float* __restrict__ k,
                        const float* __restrict__ v,
                        float* __restrict__ out_a,
                        float* __restrict__ out_w)
{
    extern __shared__ float smem[];
    float* q_tile  = smem + SM_Q;
    float* kv_tile = smem + SM_KV;
    float* scores  = smem + SM_SC;

    const int b  = blockIdx.z;
    const int h  = blockIdx.y;
    const int q0 = blockIdx.x * BQ;

    const int tid  = threadIdx.x;
    const int lane = tid & 31;
    const int warp = tid >> 5;

    // ---- load Q tile: 16 rows x 64 floats = 256 float4 loads ----
    {
        int row = tid >> 4;           // 0..15
        int c4  = (tid & 15) * 4;     // 0..60
        float4 qv = *(const float4*)&q[((size_t)(b * SS + q0 + row)) * DF + h * HD + c4];
        *(float4*)&q_tile[row * HD + c4] = qv;
    }
    __syncthreads();

    const float scale = 0.125f;  // 1/sqrt(64)

    // ---- QK^T phase: warp w owns q rows 2w, 2w+1 ----
    const int qa = warp * 2;
    const int qb = qa + 1;

    for (int ch = 0; ch < NCHUNK; ch++) {
        __syncthreads();  // previous chunk's readers done before overwrite
        // load K chunk: smem row r <- global k row s = (ch*CK + r)*STRIDE
        {
            int c4 = (tid & 15) * 4;
            int r0 = tid >> 4;
            #pragma unroll
            for (int j = 0; j < CK / 16; j++) {
                int r  = r0 + j * 16;
                int kr = ch * CK + r;
                float4 kv = *(const float4*)&k[((size_t)(b * SS + kr * STRIDE)) * DF + h * HD + c4];
                *(float4*)&kv_tile[r * KST + c4] = kv;
            }
        }
        __syncthreads();

        for (int kb = 0; kb < CK; kb += 32) {
            const float* kp = &kv_tile[(kb + lane) * KST];
            // 4 independent FMA chains per dot to cover FFMA lat=4
            float4 a0 = make_float4(0.f, 0.f, 0.f, 0.f);
            float4 a1 = make_float4(0.f, 0.f, 0.f, 0.f);
            #pragma unroll
            for (int d = 0; d < HD; d += 4) {
                float4 kv  = *(const float4*)(kp + d);
                float4 qva = *(const float4*)(q_tile + qa * HD + d);
                float4 qvb = *(const float4*)(q_tile + qb * HD + d);
                a0.x = fmaf(qva.x, kv.x, a0.x);
                a0.y = fmaf(qva.y, kv.y, a0.y);
                a0.z = fmaf(qva.z, kv.z, a0.z);
                a0.w = fmaf(qva.w, kv.w, a0.w);
                a1.x = fmaf(qvb.x, kv.x, a1.x);
                a1.y = fmaf(qvb.y, kv.y, a1.y);
                a1.z = fmaf(qvb.z, kv.z, a1.z);
                a1.w = fmaf(qvb.w, kv.w, a1.w);
            }
            int col = ch * CK + kb + lane;
            scores[qa * SK + col] = (a0.x + a0.y + a0.z + a0.w) * scale;
            scores[qb * SK + col] = (a1.x + a1.y + a1.z + a1.w) * scale;
        }
    }

    // ---- softmax (warp-local: each warp normalizes its own 2 rows) ----
    for (int rq = qa; rq <= qb; rq++) {
        float* row = &scores[rq * SK];

        float m = -1e30f;
        #pragma unroll 8
        for (int j = lane; j < SK; j += 32) m = fmaxf(m, row[j]);
        #pragma unroll
        for (int o = 16; o > 0; o >>= 1) m = fmaxf(m, __shfl_xor_sync(0xFFFFFFFFu, m, o));

        float ssum = 0.f;
        #pragma unroll 8
        for (int j = lane; j < SK; j += 32) {
            float e = __expf(row[j] - m);
            row[j] = e;
            ssum += e;
        }
        #pragma unroll
        for (int o = 16; o > 0; o >>= 1) ssum += __shfl_xor_sync(0xFFFFFFFFu, ssum, o);

        float inv = 1.0f / ssum;
        float* wrow = &out_w[(((size_t)(b * HH + h)) * SS + (q0 + rq)) * SK];
        #pragma unroll
        for (int j = lane * 4; j < SK; j += 128) {
            float4 e = *(float4*)&row[j];
            e.x *= inv; e.y *= inv; e.z *= inv; e.w *= inv;
            *(float4*)&row[j]  = e;   // keep normalized for PV
            *(float4*)&wrow[j] = e;   // emit w (coalesced STG.128)
        }
    }

    // ---- PV phase: a[q][d] = sum_k w[q][k] * V[k][d] ----
    const int pq = tid >> 4;            // 0..15  (same rows this warp normalized)
    const int pc = (tid & 15) * 4;      // 0..60
    float4 acc = make_float4(0.f, 0.f, 0.f, 0.f);
    const float* srow = &scores[pq * SK];

    for (int ch = 0; ch < NCHUNK; ch++) {
        __syncthreads();  // all warps past softmax / previous chunk reads
        {
            int c4 = (tid & 15) * 4;
            int r0 = tid >> 4;
            #pragma unroll
            for (int j = 0; j < CK / 16; j++) {
                int r  = r0 + j * 16;
                int kr = ch * CK + r;
                float4 vv = *(const float4*)&v[((size_t)(b * SS + kr * STRIDE)) * DF + h * HD + c4];
                *(float4*)&kv_tile[r * KST + c4] = vv;
            }
        }
        __syncthreads();

        #pragma unroll 4
        for (int kr = 0; kr < CK; kr++) {
            float  wv = srow[ch * CK + kr];
            float4 vv = *(const float4*)&kv_tile[kr * KST + pc];
            acc.x = fmaf(wv, vv.x, acc.x);
            acc.y = fmaf(wv, vv.y, acc.y);
            acc.z = fmaf(wv, vv.z, acc.z);
            acc.w = fmaf(wv, vv.w, acc.w);
        }
    }

    *(float4*)&out_a[((size_t)(b * SS + q0 + pq)) * DF + h * HD + pc] = acc;
}

extern "C" void kernel_launch(void* const* d_in, const int* in_sizes, int n_in,
                              void* d_out, int out_size)
{
    (void)in_sizes; (void)n_in; (void)out_size;
    const float* q = (const float*)d_in[0];
    const float* k = (const float*)d_in[1];
    const float* v = (const float*)d_in[2];

    float* out_a = (float*)d_out;
    float* out_w = out_a + (size_t)BB * SS * DF;  // w follows a (reference return order)

    cudaFuncSetAttribute(sparse_attn_kernel,
                         cudaFuncAttributeMaxDynamicSharedMemorySize, SM_BYTES);

    dim3 grid(SS / BQ, HH, BB);   // (256, 16, 4)
    sparse_attn_kernel<<<grid, NTHREADS, SM_BYTES>>>(q, k, v, out_a, out_w);
}

// round 4
// speedup vs baseline: 5.0965x; 5.0965x over previous
#include <cuda_runtime.h>
#include <cstdint>

// Problem constants
#define BB 4
#define SS 4096
#define DF 1024
#define HH 16
#define HD 64
#define SK 1024          // SS / STRIDE
#define STRIDE 4
#define BQ 128           // q rows per CTA
#define BK 64            // k cols per block
#define NBLK (SK / BK)   // 16
#define NT 256
#define PAD 68           // floats per row, Q/K/P tiles
#define VPAD 72          // floats per row, V tiles (conflict-free PV b-frags)

// smem byte offsets
#define SM_QHI 0
#define SM_QLO 34816
#define SM_P   69632
#define SM_K0  104448
#define SM_K1  121856
#define SM_V0  139264
#define SM_V1  157696
#define SM_TOTAL 176128

__device__ __forceinline__ uint32_t smem_u32(const void* p) {
    uint32_t a;
    asm("{ .reg .u64 t; cvta.to.shared.u64 t, %1; cvt.u32.u64 %0, t; }" : "=r"(a) : "l"(p));
    return a;
}

#define CP_ASYNC16(sa, gp) \
    asm volatile("cp.async.cg.shared.global [%0], [%1], 16;" :: "r"(sa), "l"(gp) : "memory")
#define CP_COMMIT() asm volatile("cp.async.commit_group;" ::: "memory")
#define CP_WAIT(N)  asm volatile("cp.async.wait_group %0;" :: "n"(N) : "memory")

// D += A * B  (m16n8k8, tf32 in, f32 out). A row-major, B col-major fragments.
__device__ __forceinline__ void mma_tf32(float c[4], const float a[4], const float b[2]) {
    asm volatile(
        "mma.sync.aligned.m16n8k8.row.col.f32.tf32.tf32.f32 "
        "{%0,%1,%2,%3}, {%4,%5,%6,%7}, {%8,%9}, {%0,%1,%2,%3};"
        : "+f"(c[0]), "+f"(c[1]), "+f"(c[2]), "+f"(c[3])
        : "r"(__float_as_uint(a[0])), "r"(__float_as_uint(a[1])),
          "r"(__float_as_uint(a[2])), "r"(__float_as_uint(a[3])),
          "r"(__float_as_uint(b[0])), "r"(__float_as_uint(b[1])));
}

// truncate to tf32 (exact hi part for Dekker split)
__device__ __forceinline__ float tf32_hi(float x) {
    return __uint_as_float(__float_as_uint(x) & 0xFFFFE000u);
}
// round-to-nearest tf32 (unbiased; HW mma would otherwise truncate)
__device__ __forceinline__ float tf32_rn(float x) {
    return __uint_as_float((__float_as_uint(x) + 0x1000u) & 0xFFFFE000u);
}

__global__ __launch_bounds__(NT, 1)
void attn_mma_kernel(const float* __restrict__ gq, const float* __restrict__ gk,
                     const float* __restrict__ gv, float* __restrict__ out_a,
                     float* __restrict__ out_w)
{
    extern __shared__ char sm[];
    const uint32_t smb = smem_u32(sm);
    float* qhi  = (float*)(sm + SM_QHI);
    float* qlo  = (float*)(sm + SM_QLO);
    float* pblk = (float*)(sm + SM_P);

    const int tid = threadIdx.x, lane = tid & 31, warp = tid >> 5;
    const int gid = lane >> 2, gc = lane & 3;           // fragment row-group / col
    const int b = blockIdx.z, h = blockIdx.y, q0 = blockIdx.x * BQ;
    const int r0 = warp * 16 + gid;                      // this thread's base q-row

    const float* kbase = gk + (size_t)b * SS * DF + h * HD;
    const float* vbase = gv + (size_t)b * SS * DF + h * HD;

    // ---- issue K/V block 0 via cp.async ----
    {
        const uint32_t ks = smb + SM_K0, vs = smb + SM_V0;
        #pragma unroll
        for (int i = 0; i < 4; i++) {
            int idx = tid + i * NT;          // 0..1023
            int r = idx >> 4, c = idx & 15;  // row 0..63, 16B chunk 0..15
            size_t goff = (size_t)(r * STRIDE) * DF + c * 4;
            CP_ASYNC16(ks + (uint32_t)(r * PAD + c * 4) * 4,  kbase + goff);
            CP_ASYNC16(vs + (uint32_t)(r * VPAD + c * 4) * 4, vbase + goff);
        }
        CP_COMMIT();
    }

    // ---- Q tile: scale by 1/8 and split into tf32 hi/lo pair (exact split) ----
    {
        const float* qb = gq + ((size_t)(b * SS + q0)) * DF + h * HD;
        #pragma unroll
        for (int i = 0; i < 8; i++) {
            int idx = tid + i * NT;          // 0..2047
            int r = idx >> 4, c4 = (idx & 15) << 2;
            float4 x = *(const float4*)&qb[(size_t)r * DF + c4];
            x.x *= 0.125f; x.y *= 0.125f; x.z *= 0.125f; x.w *= 0.125f;
            float4 hi = make_float4(tf32_hi(x.x), tf32_hi(x.y), tf32_hi(x.z), tf32_hi(x.w));
            float4 lo = make_float4(x.x - hi.x, x.y - hi.y, x.z - hi.z, x.w - hi.w);
            *(float4*)&qhi[r * PAD + c4] = hi;
            *(float4*)&qlo[r * PAD + c4] = lo;
        }
    }

    float Acc[8][4];
    #pragma unroll
    for (int t = 0; t < 8; t++) {
        Acc[t][0] = 0.f; Acc[t][1] = 0.f; Acc[t][2] = 0.f; Acc[t][3] = 0.f;
    }
    float rs0 = 0.f, rs1 = 0.f;

    for (int blk = 0; blk < NBLK; blk++) {
        // prefetch next block, then wait for current
        if (blk + 1 < NBLK) {
            const uint32_t ks = smb + (((blk + 1) & 1) ? SM_K1 : SM_K0);
            const uint32_t vs = smb + (((blk + 1) & 1) ? SM_V1 : SM_V0);
            #pragma unroll
            for (int i = 0; i < 4; i++) {
                int idx = tid + i * NT;
                int r = idx >> 4, c = idx & 15;
                size_t goff = (size_t)(((blk + 1) * BK + r) * STRIDE) * DF + c * 4;
                CP_ASYNC16(ks + (uint32_t)(r * PAD + c * 4) * 4,  kbase + goff);
                CP_ASYNC16(vs + (uint32_t)(r * VPAD + c * 4) * 4, vbase + goff);
            }
            CP_COMMIT();
            CP_WAIT(1);
        } else {
            CP_WAIT(0);
        }
        __syncthreads();   // K/V(blk) ready; also: previous PV done -> pblk free

        const float* kb = (const float*)(sm + ((blk & 1) ? SM_K1 : SM_K0));
        const float* vb = (const float*)(sm + ((blk & 1) ? SM_V1 : SM_V0));

        // ---- S = Q * K^T  (Q exact hi/lo split, K rounded RN) ----
        float S[8][4];
        #pragma unroll
        for (int t = 0; t < 8; t++) {
            S[t][0] = 0.f; S[t][1] = 0.f; S[t][2] = 0.f; S[t][3] = 0.f;
        }
        #pragma unroll
        for (int ks = 0; ks < 8; ks++) {
            float ah[4], al[4];
            ah[0] = qhi[r0 * PAD + ks * 8 + gc];
            ah[1] = qhi[(r0 + 8) * PAD + ks * 8 + gc];
            ah[2] = qhi[r0 * PAD + ks * 8 + gc + 4];
            ah[3] = qhi[(r0 + 8) * PAD + ks * 8 + gc + 4];
            al[0] = qlo[r0 * PAD + ks * 8 + gc];
            al[1] = qlo[(r0 + 8) * PAD + ks * 8 + gc];
            al[2] = qlo[r0 * PAD + ks * 8 + gc + 4];
            al[3] = qlo[(r0 + 8) * PAD + ks * 8 + gc + 4];
            #pragma unroll
            for (int t = 0; t < 8; t++) {
                float bf[2];
                bf[0] = tf32_rn(kb[(t * 8 + gid) * PAD + ks * 8 + gc]);
                bf[1] = tf32_rn(kb[(t * 8 + gid) * PAD + ks * 8 + gc + 4]);
                mma_tf32(S[t], ah, bf);
                mma_tf32(S[t], al, bf);
            }
        }

        // ---- exp, row-sum, P->smem, unnormalized w->gmem ----
        float* wr0 = out_w + (((size_t)(b * HH + h)) * SS + q0 + r0) * SK + blk * BK;
        float* wr1 = wr0 + (size_t)8 * SK;
        #pragma unroll
        for (int t = 0; t < 8; t++) {
            float p0 = __expf(S[t][0]), p1 = __expf(S[t][1]);
            float p2 = __expf(S[t][2]), p3 = __expf(S[t][3]);
            rs0 += p0 + p1;
            rs1 += p2 + p3;
            int col = t * 8 + 2 * gc;
            *(float2*)&pblk[r0 * PAD + col]       = make_float2(p0, p1);
            *(float2*)&pblk[(r0 + 8) * PAD + col] = make_float2(p2, p3);
            *(float2*)&wr0[col] = make_float2(p0, p1);
            *(float2*)&wr1[col] = make_float2(p2, p3);
        }
        __syncthreads();   // pblk fully written

        // ---- A += P * V  (P exact hi/lo split, V rounded RN) ----
        #pragma unroll
        for (int ks = 0; ks < 8; ks++) {
            float ap[4], aph[4], apl[4];
            ap[0] = pblk[r0 * PAD + ks * 8 + gc];
            ap[1] = pblk[(r0 + 8) * PAD + ks * 8 + gc];
            ap[2] = pblk[r0 * PAD + ks * 8 + gc + 4];
            ap[3] = pblk[(r0 + 8) * PAD + ks * 8 + gc + 4];
            #pragma unroll
            for (int i = 0; i < 4; i++) {
                aph[i] = tf32_hi(ap[i]);
                apl[i] = ap[i] - aph[i];
            }
            #pragma unroll
            for (int t = 0; t < 8; t++) {
                float bf[2];
                bf[0] = tf32_rn(vb[(ks * 8 + gc) * VPAD + t * 8 + gid]);
                bf[1] = tf32_rn(vb[(ks * 8 + gc + 4) * VPAD + t * 8 + gid]);
                mma_tf32(Acc[t], aph, bf);
                mma_tf32(Acc[t], apl, bf);
            }
        }
    }

    // ---- row sums -> inverses (quad reduce; all 4 lanes get the total) ----
    rs0 += __shfl_xor_sync(0xFFFFFFFFu, rs0, 1);
    rs0 += __shfl_xor_sync(0xFFFFFFFFu, rs0, 2);
    rs1 += __shfl_xor_sync(0xFFFFFFFFu, rs1, 1);
    rs1 += __shfl_xor_sync(0xFFFFFFFFu, rs1, 2);
    const float inv0 = 1.0f / rs0, inv1 = 1.0f / rs1;

    // ---- a: normalize accumulators and store ----
    {
        float* ar0 = out_a + ((size_t)(b * SS + q0 + r0)) * DF + h * HD;
        float* ar1 = ar0 + (size_t)8 * DF;
        #pragma unroll
        for (int t = 0; t < 8; t++) {
            int col = t * 8 + 2 * gc;
            *(float2*)&ar0[col] = make_float2(Acc[t][0] * inv0, Acc[t][1] * inv0);
            *(float2*)&ar1[col] = make_float2(Acc[t][2] * inv1, Acc[t][3] * inv1);
        }
    }

    // ---- w: rescale in place (L2-resident re-read) ----
    {
        float* w0 = out_w + (((size_t)(b * HH + h)) * SS + q0 + r0) * SK;
        float* w1 = w0 + (size_t)8 * SK;
        #pragma unroll 4
        for (int j = 0; j < 64; j++) {
            int c = gc * 4 + j * 16;
            float4 t0 = *(float4*)&w0[c];
            t0.x *= inv0; t0.y *= inv0; t0.z *= inv0; t0.w *= inv0;
            *(float4*)&w0[c] = t0;
            float4 t1 = *(float4*)&w1[c];
            t1.x *= inv1; t1.y *= inv1; t1.z *= inv1; t1.w *= inv1;
            *(float4*)&w1[c] = t1;
        }
    }
}

extern "C" void kernel_launch(void* const* d_in, const int* in_sizes, int n_in,
                              void* d_out, int out_size)
{
    (void)in_sizes; (void)n_in; (void)out_size;
    const float* q = (const float*)d_in[0];
    const float* k = (const float*)d_in[1];
    const float* v = (const float*)d_in[2];

    float* out_a = (float*)d_out;
    float* out_w = out_a + (size_t)BB * SS * DF;  // w follows a

    cudaFuncSetAttribute(attn_mma_kernel,
                         cudaFuncAttributeMaxDynamicSharedMemorySize, SM_TOTAL);

    dim3 grid(SS / BQ, HH, BB);   // (32, 16, 4) = 2048 CTAs
    attn_mma_kernel<<<grid, NT, SM_TOTAL>>>(q, k, v, out_a, out_w);
}

// round 5
// speedup vs baseline: 5.7703x; 1.1322x over previous
#include <cuda_runtime.h>
#include <cstdint>

// Problem constants
#define BB 4
#define SS 4096
#define DF 1024
#define HH 16
#define HD 64
#define SK 1024          // SS / STRIDE
#define STRIDE 4
#define BQ 128           // q rows per CTA
#define BK 64            // k cols per block
#define NBLK (SK / BK)   // 16
#define NT 256
#define PAD 68           // floats per row (conflict-free for all frag patterns)

// smem byte offsets
#define SM_Q   0                 // 128*68*4 = 34816
#define SM_K0  34816
#define SM_K1  52224
#define SM_V0  69632
#define SM_V1  87040
#define SM_TOTAL 104448

__device__ __forceinline__ uint32_t smem_u32(const void* p) {
    uint32_t a;
    asm("{ .reg .u64 t; cvta.to.shared.u64 t, %1; cvt.u32.u64 %0, t; }" : "=r"(a) : "l"(p));
    return a;
}

#define CP_ASYNC16(sa, gp) \
    asm volatile("cp.async.cg.shared.global [%0], [%1], 16;" :: "r"(sa), "l"(gp) : "memory")
#define CP_COMMIT() asm volatile("cp.async.commit_group;" ::: "memory")
#define CP_WAIT(N)  asm volatile("cp.async.wait_group %0;" :: "n"(N) : "memory")

// D += A * B  (m16n8k8, tf32 in, f32 out). A row-major, B col-major fragments.
__device__ __forceinline__ void mma_tf32(float c[4], const float a[4], const float b[2]) {
    asm volatile(
        "mma.sync.aligned.m16n8k8.row.col.f32.tf32.tf32.f32 "
        "{%0,%1,%2,%3}, {%4,%5,%6,%7}, {%8,%9}, {%0,%1,%2,%3};"
        : "+f"(c[0]), "+f"(c[1]), "+f"(c[2]), "+f"(c[3])
        : "r"(__float_as_uint(a[0])), "r"(__float_as_uint(a[1])),
          "r"(__float_as_uint(a[2])), "r"(__float_as_uint(a[3])),
          "r"(__float_as_uint(b[0])), "r"(__float_as_uint(b[1])));
}

// truncate to tf32 (exact hi part for Dekker split)
__device__ __forceinline__ float tf32_hi(float x) {
    return __uint_as_float(__float_as_uint(x) & 0xFFFFE000u);
}
// round-to-nearest tf32 (unbiased; HW mma truncates otherwise)
__device__ __forceinline__ float tf32_rn(float x) {
    return __uint_as_float((__float_as_uint(x) + 0x1000u) & 0xFFFFE000u);
}

__global__ __launch_bounds__(NT, 2)
void attn_mma_kernel(const float* __restrict__ gq, const float* __restrict__ gk,
                     const float* __restrict__ gv, float* __restrict__ out_a,
                     float* __restrict__ out_w)
{
    extern __shared__ char sm[];
    const uint32_t smb = smem_u32(sm);
    float* qs = (float*)(sm + SM_Q);

    const int tid = threadIdx.x, lane = tid & 31, warp = tid >> 5;
    const int gid = lane >> 2, gc = lane & 3;            // fragment row-group / col
    const int b = blockIdx.z, h = blockIdx.y, q0 = blockIdx.x * BQ;
    const int r0 = warp * 16 + gid;                      // this thread's base q-row

    const float* kbase = gk + (size_t)b * SS * DF + h * HD;
    const float* vbase = gv + (size_t)b * SS * DF + h * HD;

    // ---- issue K/V block 0 via cp.async ----
    {
        const uint32_t ks_ = smb + SM_K0, vs_ = smb + SM_V0;
        #pragma unroll
        for (int i = 0; i < 4; i++) {
            int idx = tid + i * NT;          // 0..1023
            int r = idx >> 4, c = idx & 15;  // row 0..63, 16B chunk 0..15
            size_t goff = (size_t)(r * STRIDE) * DF + c * 4;
            CP_ASYNC16(ks_ + (uint32_t)(r * PAD + c * 4) * 4, kbase + goff);
            CP_ASYNC16(vs_ + (uint32_t)(r * PAD + c * 4) * 4, vbase + goff);
        }
        CP_COMMIT();
    }

    // ---- Q tile: scale by 1/8, store full fp32 (split happens at frag load) ----
    {
        const float* qb = gq + ((size_t)(b * SS + q0)) * DF + h * HD;
        #pragma unroll
        for (int i = 0; i < 8; i++) {
            int idx = tid + i * NT;          // 0..2047
            int r = idx >> 4, c4 = (idx & 15) << 2;
            float4 x = *(const float4*)&qb[(size_t)r * DF + c4];
            x.x *= 0.125f; x.y *= 0.125f; x.z *= 0.125f; x.w *= 0.125f;
            *(float4*)&qs[r * PAD + c4] = x;
        }
    }

    float Acc[8][4];
    #pragma unroll
    for (int t = 0; t < 8; t++) {
        Acc[t][0] = 0.f; Acc[t][1] = 0.f; Acc[t][2] = 0.f; Acc[t][3] = 0.f;
    }
    float rs0 = 0.f, rs1 = 0.f;

    for (int blk = 0; blk < NBLK; blk++) {
        CP_WAIT(0);
        __syncthreads();   // K/V(blk) visible to all; all warps done reading buf^1

        // prefetch next block (safe: everyone passed the sync above)
        if (blk + 1 < NBLK) {
            const uint32_t ks_ = smb + (((blk + 1) & 1) ? SM_K1 : SM_K0);
            const uint32_t vs_ = smb + (((blk + 1) & 1) ? SM_V1 : SM_V0);
            #pragma unroll
            for (int i = 0; i < 4; i++) {
                int idx = tid + i * NT;
                int r = idx >> 4, c = idx & 15;
                size_t goff = (size_t)(((blk + 1) * BK + r) * STRIDE) * DF + c * 4;
                CP_ASYNC16(ks_ + (uint32_t)(r * PAD + c * 4) * 4, kbase + goff);
                CP_ASYNC16(vs_ + (uint32_t)(r * PAD + c * 4) * 4, vbase + goff);
            }
            CP_COMMIT();
        }

        const float* kb = (const float*)(sm + ((blk & 1) ? SM_K1 : SM_K0));
        const float* vb = (const float*)(sm + ((blk & 1) ? SM_V1 : SM_V0));

        // ---- S = Q * K^T  (Q Dekker hi/lo split at load, K rounded RN) ----
        float S[8][4];
        #pragma unroll
        for (int t = 0; t < 8; t++) {
            S[t][0] = 0.f; S[t][1] = 0.f; S[t][2] = 0.f; S[t][3] = 0.f;
        }
        #pragma unroll
        for (int ks = 0; ks < 8; ks++) {
            float x0 = qs[r0 * PAD + ks * 8 + gc];
            float x1 = qs[(r0 + 8) * PAD + ks * 8 + gc];
            float x2 = qs[r0 * PAD + ks * 8 + gc + 4];
            float x3 = qs[(r0 + 8) * PAD + ks * 8 + gc + 4];
            float ah[4], al[4];
            ah[0] = tf32_hi(x0); al[0] = x0 - ah[0];
            ah[1] = tf32_hi(x1); al[1] = x1 - ah[1];
            ah[2] = tf32_hi(x2); al[2] = x2 - ah[2];
            ah[3] = tf32_hi(x3); al[3] = x3 - ah[3];
            #pragma unroll
            for (int t = 0; t < 8; t++) {
                float bf[2];
                bf[0] = tf32_rn(kb[(t * 8 + gid) * PAD + ks * 8 + gc]);
                bf[1] = tf32_rn(kb[(t * 8 + gid) * PAD + ks * 8 + gc + 4]);
                mma_tf32(S[t], ah, bf);
                mma_tf32(S[t], al, bf);
            }
        }

        // ---- exp, row-sum, unnormalized w->gmem; S becomes P (RN'd) in-place ----
        float* wr0 = out_w + (((size_t)(b * HH + h)) * SS + q0 + r0) * SK + blk * BK;
        float* wr1 = wr0 + (size_t)8 * SK;
        #pragma unroll
        for (int t = 0; t < 8; t++) {
            float p0 = __expf(S[t][0]), p1 = __expf(S[t][1]);
            float p2 = __expf(S[t][2]), p3 = __expf(S[t][3]);
            rs0 += p0 + p1;
            rs1 += p2 + p3;
            int col = t * 8 + 2 * gc;
            *(float2*)&wr0[col] = make_float2(p0, p1);
            *(float2*)&wr1[col] = make_float2(p2, p3);
            S[t][0] = tf32_rn(p0); S[t][1] = tf32_rn(p1);
            S[t][2] = tf32_rn(p2); S[t][3] = tf32_rn(p3);
        }

        // ---- A += P * V  directly from C-fragments (k-slot permutation ψ) ----
        // A-frag slots: {c0, c2, c1, c3}; B-frag rows: 2gc, 2gc+1 (logical k)
        #pragma unroll
        for (int ks = 0; ks < 8; ks++) {
            float ap[4];
            ap[0] = S[ks][0]; ap[1] = S[ks][2];
            ap[2] = S[ks][1]; ap[3] = S[ks][3];
            #pragma unroll
            for (int t = 0; t < 8; t++) {
                float bf[2];
                bf[0] = tf32_rn(vb[(ks * 8 + 2 * gc)     * PAD + t * 8 + gid]);
                bf[1] = tf32_rn(vb[(ks * 8 + 2 * gc + 1) * PAD + t * 8 + gid]);
                mma_tf32(Acc[t], ap, bf);
            }
        }
    }

    // ---- row sums -> inverses (quad reduce; all 4 lanes get the total) ----
    rs0 += __shfl_xor_sync(0xFFFFFFFFu, rs0, 1);
    rs0 += __shfl_xor_sync(0xFFFFFFFFu, rs0, 2);
    rs1 += __shfl_xor_sync(0xFFFFFFFFu, rs1, 1);
    rs1 += __shfl_xor_sync(0xFFFFFFFFu, rs1, 2);
    const float inv0 = 1.0f / rs0, inv1 = 1.0f / rs1;

    // ---- a: normalize accumulators and store ----
    {
        float* ar0 = out_a + ((size_t)(b * SS + q0 + r0)) * DF + h * HD;
        float* ar1 = ar0 + (size_t)8 * DF;
        #pragma unroll
        for (int t = 0; t < 8; t++) {
            int col = t * 8 + 2 * gc;
            *(float2*)&ar0[col] = make_float2(Acc[t][0] * inv0, Acc[t][1] * inv0);
            *(float2*)&ar1[col] = make_float2(Acc[t][2] * inv1, Acc[t][3] * inv1);
        }
    }

    // ---- w: rescale in place (L2-resident re-read) ----
    {
        float* w0 = out_w + (((size_t)(b * HH + h)) * SS + q0 + r0) * SK;
        float* w1 = w0 + (size_t)8 * SK;
        #pragma unroll 4
        for (int j = 0; j < 64; j++) {
            int c = gc * 4 + j * 16;
            float4 t0 = *(float4*)&w0[c];
            t0.x *= inv0; t0.y *= inv0; t0.z *= inv0; t0.w *= inv0;
            *(float4*)&w0[c] = t0;
            float4 t1 = *(float4*)&w1[c];
            t1.x *= inv1; t1.y *= inv1; t1.z *= inv1; t1.w *= inv1;
            *(float4*)&w1[c] = t1;
        }
    }
}

extern "C" void kernel_launch(void* const* d_in, const int* in_sizes, int n_in,
                              void* d_out, int out_size)
{
    (void)in_sizes; (void)n_in; (void)out_size;
    const float* q = (const float*)d_in[0];
    const float* k = (const float*)d_in[1];
    const float* v = (const float*)d_in[2];

    float* out_a = (float*)d_out;
    float* out_w = out_a + (size_t)BB * SS * DF;  // w follows a

    cudaFuncSetAttribute(attn_mma_kernel,
                         cudaFuncAttributeMaxDynamicSharedMemorySize, SM_TOTAL);

    dim3 grid(SS / BQ, HH, BB);   // (32, 16, 4) = 2048 CTAs
    attn_mma_kernel<<<grid, NT, SM_TOTAL>>>(q, k, v, out_a, out_w);
}

// round 6
// speedup vs baseline: 6.9477x; 1.2040x over previous
#include <cuda_runtime.h>
#include <cstdint>

// Problem constants
#define BB 4
#define SS 4096
#define DF 1024
#define HH 16
#define HD 64
#define SK 1024          // SS / STRIDE
#define STRIDE 4
#define BQ 128           // q rows per CTA
#define BK 64            // k cols per block
#define NBLK (SK / BK)   // 16
#define NT 256
#define PAD 68           // floats per row (conflict-free for all frag patterns)
#define KSTG 17408       // bytes per 64x68 float stage

// smem byte offsets: Q + 4 stages (pass1: K ring x4; pass2: K0,K1,V0,V1)
#define SM_Q   0                 // 128*68*4 = 34816
#define SM_S0  34816
#define SM_S1  (SM_S0 + KSTG)
#define SM_S2  (SM_S0 + 2*KSTG)
#define SM_S3  (SM_S0 + 3*KSTG)
#define SM_TOTAL (SM_S0 + 4*KSTG)   // 104448

__device__ __forceinline__ uint32_t smem_u32(const void* p) {
    uint32_t a;
    asm("{ .reg .u64 t; cvta.to.shared.u64 t, %1; cvt.u32.u64 %0, t; }" : "=r"(a) : "l"(p));
    return a;
}

#define CP_ASYNC16(sa, gp) \
    asm volatile("cp.async.cg.shared.global [%0], [%1], 16;" :: "r"(sa), "l"(gp) : "memory")
#define CP_COMMIT() asm volatile("cp.async.commit_group;" ::: "memory")
#define CP_WAIT(N)  asm volatile("cp.async.wait_group %0;" :: "n"(N) : "memory")

// D += A * B  (m16n8k8, tf32 in, f32 out). A row-major, B col-major fragments.
__device__ __forceinline__ void mma_tf32(float c[4], const float a[4], const float b[2]) {
    asm volatile(
        "mma.sync.aligned.m16n8k8.row.col.f32.tf32.tf32.f32 "
        "{%0,%1,%2,%3}, {%4,%5,%6,%7}, {%8,%9}, {%0,%1,%2,%3};"
        : "+f"(c[0]), "+f"(c[1]), "+f"(c[2]), "+f"(c[3])
        : "r"(__float_as_uint(a[0])), "r"(__float_as_uint(a[1])),
          "r"(__float_as_uint(a[2])), "r"(__float_as_uint(a[3])),
          "r"(__float_as_uint(b[0])), "r"(__float_as_uint(b[1])));
}

// round-to-nearest tf32 (unbiased; HW mma truncates otherwise)
__device__ __forceinline__ float tf32_rn(float x) {
    return __uint_as_float((__float_as_uint(x) + 0x1000u) & 0xFFFFE000u);
}

__global__ __launch_bounds__(NT, 2)
void attn_mma_kernel(const float* __restrict__ gq, const float* __restrict__ gk,
                     const float* __restrict__ gv, float* __restrict__ out_a,
                     float* __restrict__ out_w)
{
    extern __shared__ char sm[];
    const uint32_t smb = smem_u32(sm);
    float* qs = (float*)(sm + SM_Q);

    const int tid = threadIdx.x, lane = tid & 31, warp = tid >> 5;
    const int gid = lane >> 2, gc = lane & 3;            // fragment row-group / col
    const int b = blockIdx.z, h = blockIdx.y, q0 = blockIdx.x * BQ;
    const int r0 = warp * 16 + gid;                      // this thread's base q-row

    const float* kbase = gk + (size_t)b * SS * DF + h * HD;
    const float* vbase = gv + (size_t)b * SS * DF + h * HD;

    // per-thread cp.async slice coords (4 chunks per 64-row stage)
    const int lr = tid >> 4;              // rows lr, lr+16, lr+32, lr+48
    const int lc = (tid & 15) << 2;       // float offset within row

    // ---- pass-1 pre-issue: K blocks 0..2 into ring stages 0..2 ----
    #pragma unroll
    for (int pb = 0; pb < 3; pb++) {
        const uint32_t st = smb + SM_S0 + pb * KSTG;
        #pragma unroll
        for (int i = 0; i < 4; i++) {
            int r = lr + i * 16;
            CP_ASYNC16(st + (uint32_t)(r * PAD + lc) * 4,
                       kbase + (size_t)((pb * BK + r) * STRIDE) * DF + lc);
        }
        CP_COMMIT();
    }

    // ---- Q tile: scale by 1/8, pre-round to tf32 RN, store fp32 ----
    {
        const float* qb = gq + ((size_t)(b * SS + q0)) * DF + h * HD;
        #pragma unroll
        for (int i = 0; i < 8; i++) {
            int idx = tid + i * NT;          // 0..2047
            int r = idx >> 4, c4 = (idx & 15) << 2;
            float4 x = *(const float4*)&qb[(size_t)r * DF + c4];
            x.x = tf32_rn(x.x * 0.125f); x.y = tf32_rn(x.y * 0.125f);
            x.z = tf32_rn(x.z * 0.125f); x.w = tf32_rn(x.w * 0.125f);
            *(float4*)&qs[r * PAD + c4] = x;
        }
    }

    float rs0 = 0.f, rs1 = 0.f;

    // ================= PASS 1: row sums (K-only, 4-stage ring) =================
    for (int blk = 0; blk < NBLK; blk++) {
        if      (blk < NBLK - 2) CP_WAIT(2);
        else if (blk == NBLK - 2) CP_WAIT(1);
        else                      CP_WAIT(0);
        __syncthreads();   // blk data visible; all warps done reading stage (blk+3)&3

        if (blk + 3 < NBLK) {
            const uint32_t st = smb + SM_S0 + ((blk + 3) & 3) * KSTG;
            #pragma unroll
            for (int i = 0; i < 4; i++) {
                int r = lr + i * 16;
                CP_ASYNC16(st + (uint32_t)(r * PAD + lc) * 4,
                           kbase + (size_t)(((blk + 3) * BK + r) * STRIDE) * DF + lc);
            }
            CP_COMMIT();
        }

        const float* kb = (const float*)(sm + SM_S0 + (blk & 3) * KSTG);

        float S[8][4];
        #pragma unroll
        for (int t = 0; t < 8; t++) {
            S[t][0] = 0.f; S[t][1] = 0.f; S[t][2] = 0.f; S[t][3] = 0.f;
        }
        #pragma unroll
        for (int ks = 0; ks < 8; ks++) {
            float a[4];
            a[0] = qs[r0 * PAD + ks * 8 + gc];
            a[1] = qs[(r0 + 8) * PAD + ks * 8 + gc];
            a[2] = qs[r0 * PAD + ks * 8 + gc + 4];
            a[3] = qs[(r0 + 8) * PAD + ks * 8 + gc + 4];
            #pragma unroll
            for (int t = 0; t < 8; t++) {
                float bf[2];
                bf[0] = tf32_rn(kb[(t * 8 + gid) * PAD + ks * 8 + gc]);
                bf[1] = tf32_rn(kb[(t * 8 + gid) * PAD + ks * 8 + gc + 4]);
                mma_tf32(S[t], a, bf);
            }
        }
        #pragma unroll
        for (int t = 0; t < 8; t++) {
            rs0 += __expf(S[t][0]) + __expf(S[t][1]);
            rs1 += __expf(S[t][2]) + __expf(S[t][3]);
        }
    }

    // ---- row sums -> inverses (quad reduce; all 4 lanes get the total) ----
    rs0 += __shfl_xor_sync(0xFFFFFFFFu, rs0, 1);
    rs0 += __shfl_xor_sync(0xFFFFFFFFu, rs0, 2);
    rs1 += __shfl_xor_sync(0xFFFFFFFFu, rs1, 1);
    rs1 += __shfl_xor_sync(0xFFFFFFFFu, rs1, 2);
    const float inv0 = 1.0f / rs0, inv1 = 1.0f / rs1;

    __syncthreads();   // all warps done with pass-1 buffers

    // pre-issue pass-2 block 0 (K -> S0, V -> S2), one group
    {
        #pragma unroll
        for (int i = 0; i < 4; i++) {
            int r = lr + i * 16;
            size_t goff = (size_t)(r * STRIDE) * DF + lc;
            CP_ASYNC16(smb + SM_S0 + (uint32_t)(r * PAD + lc) * 4, kbase + goff);
            CP_ASYNC16(smb + SM_S2 + (uint32_t)(r * PAD + lc) * 4, vbase + goff);
        }
        CP_COMMIT();
    }

    float Acc[8][4];
    #pragma unroll
    for (int t = 0; t < 8; t++) {
        Acc[t][0] = 0.f; Acc[t][1] = 0.f; Acc[t][2] = 0.f; Acc[t][3] = 0.f;
    }

    // ================= PASS 2: w (normalized) + PV =================
    for (int blk = 0; blk < NBLK; blk++) {
        CP_WAIT(0);
        __syncthreads();   // K/V(blk) visible; all warps done reading buf^1

        if (blk + 1 < NBLK) {
            const uint32_t ks_ = smb + (((blk + 1) & 1) ? SM_S1 : SM_S0);
            const uint32_t vs_ = smb + (((blk + 1) & 1) ? SM_S3 : SM_S2);
            #pragma unroll
            for (int i = 0; i < 4; i++) {
                int r = lr + i * 16;
                size_t goff = (size_t)(((blk + 1) * BK + r) * STRIDE) * DF + lc;
                CP_ASYNC16(ks_ + (uint32_t)(r * PAD + lc) * 4, kbase + goff);
                CP_ASYNC16(vs_ + (uint32_t)(r * PAD + lc) * 4, vbase + goff);
            }
            CP_COMMIT();
        }

        const float* kb = (const float*)(sm + ((blk & 1) ? SM_S1 : SM_S0));
        const float* vb = (const float*)(sm + ((blk & 1) ? SM_S3 : SM_S2));

        // ---- S = Q * K^T  (bitwise-identical to pass 1) ----
        float S[8][4];
        #pragma unroll
        for (int t = 0; t < 8; t++) {
            S[t][0] = 0.f; S[t][1] = 0.f; S[t][2] = 0.f; S[t][3] = 0.f;
        }
        #pragma unroll
        for (int ks = 0; ks < 8; ks++) {
            float a[4];
            a[0] = qs[r0 * PAD + ks * 8 + gc];
            a[1] = qs[(r0 + 8) * PAD + ks * 8 + gc];
            a[2] = qs[r0 * PAD + ks * 8 + gc + 4];
            a[3] = qs[(r0 + 8) * PAD + ks * 8 + gc + 4];
            #pragma unroll
            for (int t = 0; t < 8; t++) {
                float bf[2];
                bf[0] = tf32_rn(kb[(t * 8 + gid) * PAD + ks * 8 + gc]);
                bf[1] = tf32_rn(kb[(t * 8 + gid) * PAD + ks * 8 + gc + 4]);
                mma_tf32(S[t], a, bf);
            }
        }

        // ---- normalized w -> gmem; S becomes normalized P (RN'd) in regs ----
        float* wr0 = out_w + (((size_t)(b * HH + h)) * SS + q0 + r0) * SK + blk * BK;
        float* wr1 = wr0 + (size_t)8 * SK;
        #pragma unroll
        for (int t = 0; t < 8; t++) {
            float p0 = __expf(S[t][0]) * inv0, p1 = __expf(S[t][1]) * inv0;
            float p2 = __expf(S[t][2]) * inv1, p3 = __expf(S[t][3]) * inv1;
            int col = t * 8 + 2 * gc;
            *(float2*)&wr0[col] = make_float2(p0, p1);
            *(float2*)&wr1[col] = make_float2(p2, p3);
            S[t][0] = tf32_rn(p0); S[t][1] = tf32_rn(p1);
            S[t][2] = tf32_rn(p2); S[t][3] = tf32_rn(p3);
        }

        // ---- A += P * V  directly from C-fragments (k-slot permutation) ----
        // A-frag slots: {c0, c2, c1, c3}; B-frag rows: 2gc, 2gc+1 (logical k)
        #pragma unroll
        for (int ks = 0; ks < 8; ks++) {
            float ap[4];
            ap[0] = S[ks][0]; ap[1] = S[ks][2];
            ap[2] = S[ks][1]; ap[3] = S[ks][3];
            #pragma unroll
            for (int t = 0; t < 8; t++) {
                float bf[2];
                bf[0] = tf32_rn(vb[(ks * 8 + 2 * gc)     * PAD + t * 8 + gid]);
                bf[1] = tf32_rn(vb[(ks * 8 + 2 * gc + 1) * PAD + t * 8 + gid]);
                mma_tf32(Acc[t], ap, bf);
            }
        }
    }

    // ---- a: already normalized, just store ----
    {
        float* ar0 = out_a + ((size_t)(b * SS + q0 + r0)) * DF + h * HD;
        float* ar1 = ar0 + (size_t)8 * DF;
        #pragma unroll
        for (int t = 0; t < 8; t++) {
            int col = t * 8 + 2 * gc;
            *(float2*)&ar0[col] = make_float2(Acc[t][0], Acc[t][1]);
            *(float2*)&ar1[col] = make_float2(Acc[t][2], Acc[t][3]);
        }
    }
}

extern "C" void kernel_launch(void* const* d_in, const int* in_sizes, int n_in,
                              void* d_out, int out_size)
{
    (void)in_sizes; (void)n_in; (void)out_size;
    const float* q = (const float*)d_in[0];
    const float* k = (const float*)d_in[1];
    const float* v = (const float*)d_in[2];

    float* out_a = (float*)d_out;
    float* out_w = out_a + (size_t)BB * SS * DF;  // w follows a

    cudaFuncSetAttribute(attn_mma_kernel,
                         cudaFuncAttributeMaxDynamicSharedMemorySize, SM_TOTAL);

    dim3 grid(SS / BQ, HH, BB);   // (32, 16, 4) = 2048 CTAs
    attn_mma_kernel<<<grid, NT, SM_TOTAL>>>(q, k, v, out_a, out_w);
}